// round 11
// baseline (speedup 1.0000x reference)
#include <cuda_runtime.h>
#include <cuda_bf16.h>
#include <stdint.h>
#include <math.h>

// Problem constants
#define BB 2
#define TT 2048
#define DM 2048
#define HH 16
#define DK 128
#define DV 128
#define KW 4
#define CDIM 6144          // 2*H*DK + H*DV
#define MTOK 4096          // B*T

// ---------------- scratch (device globals; no allocation allowed) ----------------
__device__ float g_mixed[(size_t)MTOK * CDIM];
__device__ float g_y[(size_t)MTOK * CDIM];
__device__ float g_qn[(size_t)MTOK * 2048];
__device__ float g_kn[(size_t)MTOK * 2048];
__device__ float g_beta[(size_t)MTOK * HH];
__device__ float g_decay[(size_t)MTOK * HH];
__device__ float g_o[(size_t)MTOK * 2048];
__device__ float g_z[(size_t)MTOK * 2048];
__device__ float g_on[(size_t)MTOK * 2048];

// bf16 hi/lo pre-split operands
__device__ __nv_bfloat16 g_xh[(size_t)MTOK * DM];
__device__ __nv_bfloat16 g_xl[(size_t)MTOK * DM];
__device__ __nv_bfloat16 g_wqh[(size_t)CDIM * DM];
__device__ __nv_bfloat16 g_wql[(size_t)CDIM * DM];
__device__ __nv_bfloat16 g_wzh[(size_t)2048 * DM];
__device__ __nv_bfloat16 g_wzl[(size_t)2048 * DM];
__device__ __nv_bfloat16 g_woh[(size_t)2048 * 2048];
__device__ __nv_bfloat16 g_wol[(size_t)2048 * 2048];
__device__ __nv_bfloat16 g_onh[(size_t)MTOK * 2048];
__device__ __nv_bfloat16 g_onl[(size_t)MTOK * 2048];

// ---------------- helpers ----------------
__device__ __forceinline__ void cp16(unsigned int dst, const void* src) {
    asm volatile("cp.async.cg.shared.global [%0], [%1], 16;" ::"r"(dst), "l"(src));
}

__device__ __forceinline__ unsigned short bfbits(__nv_bfloat16 v) {
    return *reinterpret_cast<unsigned short*>(&v);
}

__device__ __forceinline__ void ldsm4(unsigned int* r, unsigned int addr) {
    asm volatile("ldmatrix.sync.aligned.m8n8.x4.shared.b16 {%0,%1,%2,%3}, [%4];"
                 : "=r"(r[0]), "=r"(r[1]), "=r"(r[2]), "=r"(r[3])
                 : "r"(addr));
}

// packed f32x2 ops (sm_100+ PTX)
typedef unsigned long long ull;
__device__ __forceinline__ ull pk2(float lo, float hi) {
    ull r;
    asm("mov.b64 %0, {%1, %2};" : "=l"(r) : "f"(lo), "f"(hi));
    return r;
}
__device__ __forceinline__ void upk2(ull v, float& lo, float& hi) {
    asm("mov.b64 {%0, %1}, %2;" : "=f"(lo), "=f"(hi) : "l"(v));
}
__device__ __forceinline__ ull fma2(ull a, ull b, ull c) {
    ull d;
    asm("fma.rn.f32x2 %0, %1, %2, %3;" : "=l"(d) : "l"(a), "l"(b), "l"(c));
    return d;
}
__device__ __forceinline__ ull mul2(ull a, ull b) {
    ull d;
    asm("mul.rn.f32x2 %0, %1, %2;" : "=l"(d) : "l"(a), "l"(b));
    return d;
}

// ---------------- bf16 hi/lo split ----------------
__global__ __launch_bounds__(256) void split_bf(const float* __restrict__ s,
                                                __nv_bfloat16* __restrict__ h,
                                                __nv_bfloat16* __restrict__ l, int n4) {
    int i = blockIdx.x * 256 + threadIdx.x;
    if (i >= n4) return;
    float4 v = ((const float4*)s)[i];
    __nv_bfloat16 h0 = __float2bfloat16(v.x);
    __nv_bfloat16 h1 = __float2bfloat16(v.y);
    __nv_bfloat16 h2 = __float2bfloat16(v.z);
    __nv_bfloat16 h3 = __float2bfloat16(v.w);
    __nv_bfloat16 l0 = __float2bfloat16(v.x - __bfloat162float(h0));
    __nv_bfloat16 l1 = __float2bfloat16(v.y - __bfloat162float(h1));
    __nv_bfloat16 l2 = __float2bfloat16(v.z - __bfloat162float(h2));
    __nv_bfloat16 l3 = __float2bfloat16(v.w - __bfloat162float(h3));
    uint2 ho, lo;
    ho.x = ((unsigned int)bfbits(h1) << 16) | bfbits(h0);
    ho.y = ((unsigned int)bfbits(h3) << 16) | bfbits(h2);
    lo.x = ((unsigned int)bfbits(l1) << 16) | bfbits(l0);
    lo.y = ((unsigned int)bfbits(l3) << 16) | bfbits(l2);
    ((uint2*)h)[i] = ho;
    ((uint2*)l)[i] = lo;
}

// ---------------- 3xBF16 split tensor-core GEMM (ldmatrix inner loop) ----------
#define BKPAD 40
#define ROWB 80
#define TILE_ELE (128 * BKPAD)
#define TILE_B (TILE_ELE * 2)
#define STAGE_ELE (4 * TILE_ELE)
#define STAGE_B (4 * TILE_B)
#define GEMM_SMEM_B (2 * STAGE_B)

__device__ __forceinline__ void mma16(float* c, const unsigned int* a,
                                      unsigned int b0, unsigned int b1) {
    asm volatile(
        "mma.sync.aligned.m16n8k16.row.col.f32.bf16.bf16.f32 "
        "{%0,%1,%2,%3}, {%4,%5,%6,%7}, {%8,%9}, {%0,%1,%2,%3};"
        : "+f"(c[0]), "+f"(c[1]), "+f"(c[2]), "+f"(c[3])
        : "r"(a[0]), "r"(a[1]), "r"(a[2]), "r"(a[3]), "r"(b0), "r"(b1));
}

__device__ __forceinline__ void stage_tile(unsigned int dst, const __nv_bfloat16* src,
                                           int K, int tid) {
    const int row = tid >> 1;
    const int c0 = (tid & 1) * 2;
    cp16(dst + (unsigned int)(row * ROWB + c0 * 16), src + (size_t)row * K + c0 * 8);
    cp16(dst + (unsigned int)(row * ROWB + (c0 + 1) * 16), src + (size_t)row * K + (c0 + 1) * 8);
}

__device__ __forceinline__ void gemm_body(const __nv_bfloat16* Abh,
                                          const __nv_bfloat16* Abl,
                                          const __nv_bfloat16* Bbh,
                                          const __nv_bfloat16* Bbl,
                                          float* __restrict__ Crow0,
                                          int N, int K) {
    extern __shared__ __align__(16) __nv_bfloat16 sm[];
    const int tid = threadIdx.x;
    const int warp = tid >> 5, lane = tid & 31;
    const int wm = (warp & 3) * 32;
    const int wn = (warp >> 2) * 64;
    const int g = lane >> 2, tg = lane & 3;

    const unsigned int smb = (unsigned int)__cvta_generic_to_shared(sm);

    const unsigned int aLane =
        (unsigned int)((wm + (lane & 7) + ((lane & 8) ? 8 : 0)) * ROWB +
                       ((lane & 16) ? 16 : 0));
    const unsigned int bLane =
        (unsigned int)((wn + (lane & 7) + ((lane & 16) ? 8 : 0)) * ROWB +
                       ((lane & 8) ? 16 : 0));

    float acc[2][8][4];
#pragma unroll
    for (int mi = 0; mi < 2; mi++)
#pragma unroll
        for (int ni = 0; ni < 8; ni++)
#pragma unroll
            for (int r = 0; r < 4; r++) acc[mi][ni][r] = 0.f;

    stage_tile(smb + 0 * TILE_B, Abh, K, tid);
    stage_tile(smb + 1 * TILE_B, Abl, K, tid);
    stage_tile(smb + 2 * TILE_B, Bbh, K, tid);
    stage_tile(smb + 3 * TILE_B, Bbl, K, tid);
    asm volatile("cp.async.commit_group;");

    const int nk = K >> 5;
    for (int j = 0; j < nk; j++) {
        const int buf = j & 1;
        if (j + 1 < nk) {
            const unsigned int db = smb + (buf ^ 1) * STAGE_B;
            const int ko = (j + 1) * 32;
            stage_tile(db + 0 * TILE_B, Abh + ko, K, tid);
            stage_tile(db + 1 * TILE_B, Abl + ko, K, tid);
            stage_tile(db + 2 * TILE_B, Bbh + ko, K, tid);
            stage_tile(db + 3 * TILE_B, Bbl + ko, K, tid);
            asm volatile("cp.async.commit_group;");
            asm volatile("cp.async.wait_group 1;");
        } else {
            asm volatile("cp.async.wait_group 0;");
        }
        __syncthreads();

        const unsigned int tAh = smb + buf * STAGE_B;
        const unsigned int tAl = tAh + TILE_B;
        const unsigned int tBh = tAh + 2 * TILE_B;
        const unsigned int tBl = tAh + 3 * TILE_B;

#pragma unroll
        for (int kk = 0; kk < 32; kk += 16) {
            const unsigned int kb = (unsigned int)(kk * 2);
            unsigned int ah[2][4], al[2][4];
            ldsm4(ah[0], tAh + kb + aLane);
            ldsm4(ah[1], tAh + kb + aLane + 16 * ROWB);
            ldsm4(al[0], tAl + kb + aLane);
            ldsm4(al[1], tAl + kb + aLane + 16 * ROWB);
#pragma unroll
            for (int p = 0; p < 4; p++) {
                const unsigned int po = kb + (unsigned int)(p * 16 * ROWB) + bLane;
                unsigned int bh[4], bl[4];
                ldsm4(bh, tBh + po);
                ldsm4(bl, tBl + po);
#pragma unroll
                for (int mi = 0; mi < 2; mi++) {
                    mma16(acc[mi][2 * p], al[mi], bh[0], bh[1]);
                    mma16(acc[mi][2 * p], ah[mi], bl[0], bl[1]);
                    mma16(acc[mi][2 * p], ah[mi], bh[0], bh[1]);
                    mma16(acc[mi][2 * p + 1], al[mi], bh[2], bh[3]);
                    mma16(acc[mi][2 * p + 1], ah[mi], bl[2], bl[3]);
                    mma16(acc[mi][2 * p + 1], ah[mi], bh[2], bh[3]);
                }
            }
        }
        __syncthreads();
    }

#pragma unroll
    for (int mi = 0; mi < 2; mi++) {
#pragma unroll
        for (int ni = 0; ni < 8; ni++) {
            const int r0 = wm + mi * 16 + g;
            const int cc = wn + ni * 8 + tg * 2;
            *(float2*)(Crow0 + (size_t)r0 * N + cc) =
                make_float2(acc[mi][ni][0], acc[mi][ni][1]);
            *(float2*)(Crow0 + (size_t)(r0 + 8) * N + cc) =
                make_float2(acc[mi][ni][2], acc[mi][ni][3]);
        }
    }
}

__global__ __launch_bounds__(256, 2) void gemm_bf16(const __nv_bfloat16* __restrict__ Ah,
                                                    const __nv_bfloat16* __restrict__ Al,
                                                    const __nv_bfloat16* __restrict__ Bh,
                                                    const __nv_bfloat16* __restrict__ Bl,
                                                    float* __restrict__ C,
                                                    int M, int N, int K) {
    const int bm = blockIdx.y * 128, bn = blockIdx.x * 128;
    gemm_body(Ah + (size_t)bm * K, Al + (size_t)bm * K,
              Bh + (size_t)bn * K, Bl + (size_t)bn * K,
              C + (size_t)bm * N + bn, N, K);
}

__global__ __launch_bounds__(256, 2) void gemm_bf16_dual(
    const __nv_bfloat16* __restrict__ Ah, const __nv_bfloat16* __restrict__ Al,
    const __nv_bfloat16* __restrict__ B1h, const __nv_bfloat16* __restrict__ B1l,
    float* __restrict__ C1, int N1,
    const __nv_bfloat16* __restrict__ B2h, const __nv_bfloat16* __restrict__ B2l,
    float* __restrict__ C2, int N2, int K) {
    const int bm = blockIdx.y * 128;
    int bn = blockIdx.x * 128;
    const __nv_bfloat16 *Bh, *Bl;
    float* C;
    int N;
    if (bn < N1) {
        Bh = B1h; Bl = B1l; C = C1; N = N1;
    } else {
        bn -= N1;
        Bh = B2h; Bl = B2l; C = C2; N = N2;
    }
    gemm_body(Ah + (size_t)bm * K, Al + (size_t)bm * K,
              Bh + (size_t)bn * K, Bl + (size_t)bn * K,
              C + (size_t)bm * N + bn, N, K);
}

// ---------------- gates (tiled): 8 tokens per block, weights staged in smem ----
__global__ __launch_bounds__(256) void proj_gates(const float* __restrict__ x,
                                                  const float* __restrict__ w_b,
                                                  const float* __restrict__ w_a,
                                                  const float* __restrict__ dt_bias,
                                                  const float* __restrict__ A_log) {
    __shared__ float xs[8][260];
    __shared__ float ws[256][33];
    const int tid = threadIdx.x;
    const int d = tid & 31, tg = tid >> 5;
    const int m0 = blockIdx.x * 8;

    float acc = 0.f;
    for (int kc = 0; kc < DM; kc += 256) {
        __syncthreads();
        for (int idx = tid; idx < 8 * 256; idx += 256) {
            const int tok = idx >> 8, k = idx & 255;
            xs[tok][k] = x[(size_t)(m0 + tok) * DM + kc + k];
        }
        for (int idx = tid; idx < 32 * 256; idx += 256) {
            const int dd = idx >> 8, k = idx & 255;
            const float v = (dd < HH) ? w_b[(size_t)dd * DM + kc + k]
                                      : w_a[(size_t)(dd - HH) * DM + kc + k];
            ws[k][dd] = v;
        }
        __syncthreads();
#pragma unroll 8
        for (int k = 0; k < 256; k++) acc += xs[tg][k] * ws[k][d];
    }

    const int m = m0 + tg;
    if (d < HH) {
        g_beta[(size_t)m * HH + d] = 1.f / (1.f + expf(-acc));
    } else {
        const int h = d - HH;
        float sp = acc + dt_bias[h];
        sp = (sp > 20.f) ? sp : log1pf(expf(sp));
        g_decay[(size_t)m * HH + h] = expf(-expf(A_log[h]) * sp);
    }
}

// ---------------- causal depthwise conv + SiLU, fused q/k l2norm ----------------
__global__ __launch_bounds__(256) void conv_qk(const float* __restrict__ conv_w) {
    const int c = blockIdx.x * 256 + threadIdx.x;
    const int bt = blockIdx.y;
    const int t = bt & (TT - 1);
    const float* base = g_mixed + (size_t)bt * CDIM + c;
    float4 w = *(const float4*)(conv_w + (size_t)c * KW);
    float acc = w.w * base[0];
    if (t >= 1) acc += w.z * base[-(ptrdiff_t)CDIM];
    if (t >= 2) acc += w.y * base[-(ptrdiff_t)(2 * CDIM)];
    if (t >= 3) acc += w.x * base[-(ptrdiff_t)(3 * CDIM)];
    const float s = acc / (1.f + expf(-acc));

    if (blockIdx.x < 16) {
        // q/k region: block = exactly 2 heads of 128 channels; l2-normalize per head
        __shared__ float red[8];
        float ss = s * s;
#pragma unroll
        for (int o = 16; o; o >>= 1) ss += __shfl_xor_sync(0xffffffffu, ss, o);
        const int warp = threadIdx.x >> 5;
        if ((threadIdx.x & 31) == 0) red[warp] = ss;
        __syncthreads();
        const int grp = threadIdx.x >> 7;  // head within block
        const float tot = red[grp * 4] + red[grp * 4 + 1] + red[grp * 4 + 2] + red[grp * 4 + 3];
        const float r = rsqrtf(tot + 1e-6f);
        const int hh = c >> 7;             // 0..15 q, 16..31 k
        float* dst = (hh < HH) ? g_qn : g_kn;
        dst[(size_t)bt * 2048 + (hh & 15) * DK + (c & 127)] = s * r;
    } else {
        g_y[(size_t)bt * CDIM + c] = s;    // v region
    }
}

// ---------------- sequential delta-rule scan (f32x2, 8 k-groups x 16 j) --------
#define SK(v) ((v) + (((v) >> 4) << 1))   // pad 2 floats per 16
__global__ __launch_bounds__(128) void scan_kernel(float* __restrict__ o) {
    const int bh = blockIdx.x;
    const int b = bh >> 4, h = bh & 15;
    const int jc = blockIdx.y;             // 0..7
    const int tid = threadIdx.x;
    const int jloc = tid >> 3;             // 0..15
    const int kg = tid & 7;                // 0..7

    __shared__ float ks[2][144], qs[2][144], vs[2][16], sc[2][2];
    ull S2[8];
#pragma unroll
    for (int i = 0; i < 8; i++) S2[i] = 0ull;

    const size_t qkbase = ((size_t)b * TT) * 2048 + h * DK;
    const size_t vbase = ((size_t)b * TT) * CDIM + 2 * HH * DK + h * DV + jc * 16;
    const size_t gbase = ((size_t)b * TT) * HH + h;
    const size_t obase = ((size_t)b * TT) * 2048 + h * DV + jc * 16 + jloc;

    float rk = g_kn[qkbase + tid];
    float rq = g_qn[qkbase + tid];
    float rv = (tid < 16) ? g_y[vbase + tid] : 0.f;
    float rb = g_beta[gbase], rd = g_decay[gbase];
    ks[0][SK(tid)] = rk;
    qs[0][SK(tid)] = rq;
    if (tid < 16) vs[0][tid] = rv;
    if (tid == 0) { sc[0][0] = rb; sc[0][1] = rd; }
    __syncthreads();

    const int kbase = kg * 18;  // 16 + 2 pad per group; even -> float2 aligned

    for (int t = 0; t < TT; t++) {
        const int cur = t & 1;
        if (t + 1 < TT) {
            const size_t to = (size_t)(t + 1);
            rk = g_kn[qkbase + to * 2048 + tid];
            rq = g_qn[qkbase + to * 2048 + tid];
            if (tid < 16) rv = g_y[vbase + to * CDIM + tid];
            rb = g_beta[gbase + to * HH];
            rd = g_decay[gbase + to * HH];
        }
        const float bet = sc[cur][0];
        const float dec = sc[cur][1];
        const float vv = vs[cur][jloc];

        ull k2[8], q2[8];
#pragma unroll
        for (int i = 0; i < 8; i++) {
            const float2 kf = *(const float2*)&ks[cur][kbase + 2 * i];
            const float2 qf = *(const float2*)&qs[cur][kbase + 2 * i];
            k2[i] = pk2(kf.x, kf.y);
            q2[i] = pk2(qf.x, qf.y);
        }

        ull kv2 = 0ull;
#pragma unroll
        for (int i = 0; i < 8; i++) kv2 = fma2(k2[i], S2[i], kv2);
        float klo, khi;
        upk2(kv2, klo, khi);
        float kv = klo + khi;
        kv += __shfl_xor_sync(0xffffffffu, kv, 1);
        kv += __shfl_xor_sync(0xffffffffu, kv, 2);
        kv += __shfl_xor_sync(0xffffffffu, kv, 4);
        kv *= dec;

        const float delta = (vv - kv) * bet;
        const ull d2 = pk2(delta, delta);
        const ull dec2 = pk2(dec, dec);

        ull o2 = 0ull;
#pragma unroll
        for (int i = 0; i < 8; i++) {
            S2[i] = fma2(dec2, S2[i], mul2(k2[i], d2));
            o2 = fma2(q2[i], S2[i], o2);
        }
        float olo, ohi;
        upk2(o2, olo, ohi);
        float oacc = olo + ohi;
        oacc += __shfl_xor_sync(0xffffffffu, oacc, 1);
        oacc += __shfl_xor_sync(0xffffffffu, oacc, 2);
        oacc += __shfl_xor_sync(0xffffffffu, oacc, 4);
        if (kg == 0) o[obase + (size_t)t * 2048] = oacc;

        if (t + 1 < TT) {
            const int nxt = cur ^ 1;
            ks[nxt][SK(tid)] = rk;
            qs[nxt][SK(tid)] = rq;
            if (tid < 16) vs[nxt][tid] = rv;
            if (tid == 0) { sc[nxt][0] = rb; sc[nxt][1] = rd; }
        }
        __syncthreads();
    }
}

// ---------------- gated RMSNorm per head ----------------
__global__ __launch_bounds__(128) void gated_norm(const float* __restrict__ norm_w) {
    const int g = blockIdx.x;  // bt*16 + h
    float u = g_o[(size_t)g * DV + threadIdx.x];
    float s = u * u;
#pragma unroll
    for (int o = 16; o; o >>= 1) s += __shfl_xor_sync(0xffffffffu, s, o);
    __shared__ float red[4];
    if ((threadIdx.x & 31) == 0) red[threadIdx.x >> 5] = s;
    __syncthreads();
    float tot = red[0] + red[1] + red[2] + red[3];
    float r = rsqrtf(tot * (1.f / DV) + 1e-6f);
    float zz = g_z[(size_t)g * DV + threadIdx.x];
    float sil = zz / (1.f + expf(-zz));
    g_on[(size_t)g * DV + threadIdx.x] = u * r * norm_w[threadIdx.x] * sil;
}

// ---------------- launch ----------------
extern "C" void kernel_launch(void* const* d_in, const int* in_sizes, int n_in,
                              void* d_out, int out_size) {
    const float* x = (const float*)d_in[0];
    const float* w_qkv = (const float*)d_in[1];
    const float* conv_w = (const float*)d_in[2];
    const float* w_z = (const float*)d_in[3];
    const float* w_b = (const float*)d_in[4];
    const float* w_a = (const float*)d_in[5];
    const float* dt_bias = (const float*)d_in[6];
    const float* A_log = (const float*)d_in[7];
    const float* norm_w = (const float*)d_in[8];
    const float* w_out = (const float*)d_in[9];
    float* out = (float*)d_out;

    float *mixed, *z, *o, *on;
    __nv_bfloat16 *xh, *xl, *wqh, *wql, *wzh, *wzl, *woh, *wol, *onh, *onl;
    cudaGetSymbolAddress((void**)&mixed, g_mixed);
    cudaGetSymbolAddress((void**)&z, g_z);
    cudaGetSymbolAddress((void**)&o, g_o);
    cudaGetSymbolAddress((void**)&on, g_on);
    cudaGetSymbolAddress((void**)&xh, g_xh);
    cudaGetSymbolAddress((void**)&xl, g_xl);
    cudaGetSymbolAddress((void**)&wqh, g_wqh);
    cudaGetSymbolAddress((void**)&wql, g_wql);
    cudaGetSymbolAddress((void**)&wzh, g_wzh);
    cudaGetSymbolAddress((void**)&wzl, g_wzl);
    cudaGetSymbolAddress((void**)&woh, g_woh);
    cudaGetSymbolAddress((void**)&wol, g_wol);
    cudaGetSymbolAddress((void**)&onh, g_onh);
    cudaGetSymbolAddress((void**)&onl, g_onl);

    cudaFuncSetAttribute(gemm_bf16, cudaFuncAttributeMaxDynamicSharedMemorySize, GEMM_SMEM_B);
    cudaFuncSetAttribute(gemm_bf16_dual, cudaFuncAttributeMaxDynamicSharedMemorySize,
                         GEMM_SMEM_B);

    // bf16 hi/lo pre-splits
    split_bf<<<(MTOK * DM / 4 + 255) / 256, 256>>>(x, xh, xl, MTOK * DM / 4);
    split_bf<<<(CDIM * DM / 4 + 255) / 256, 256>>>(w_qkv, wqh, wql, CDIM * DM / 4);
    split_bf<<<(2048 * DM / 4 + 255) / 256, 256>>>(w_z, wzh, wzl, 2048 * DM / 4);
    split_bf<<<(2048 * 2048 / 4 + 255) / 256, 256>>>(w_out, woh, wol, 2048 * 2048 / 4);

    // fused qkv + z projection
    gemm_bf16_dual<<<dim3((CDIM + 2048) / 128, MTOK / 128), 256, GEMM_SMEM_B>>>(
        xh, xl, wqh, wql, mixed, CDIM, wzh, wzl, z, 2048, DM);
    // gates (tiled)
    proj_gates<<<MTOK / 8, 256>>>(x, w_b, w_a, dt_bias, A_log);
    // conv + silu + fused q/k l2norm
    conv_qk<<<dim3(CDIM / 256, MTOK), 256>>>(conv_w);
    // scan
    scan_kernel<<<dim3(BB * HH, 8), 128>>>(o);
    // gated rmsnorm
    gated_norm<<<MTOK * HH, 128>>>(norm_w);
    // split on, then out = on @ w_out^T
    split_bf<<<(MTOK * 2048 / 4 + 255) / 256, 256>>>(on, onh, onl, MTOK * 2048 / 4);
    gemm_bf16<<<dim3(2048 / 128, MTOK / 128), 256, GEMM_SMEM_B>>>(onh, onl, woh, wol, out,
                                                                  MTOK, 2048, DM);
}

// round 12
// speedup vs baseline: 1.1808x; 1.1808x over previous
#include <cuda_runtime.h>
#include <cuda_bf16.h>
#include <stdint.h>
#include <math.h>

// Problem constants
#define BB 2
#define TT 2048
#define DM 2048
#define HH 16
#define DK 128
#define DV 128
#define KW 4
#define CDIM 6144          // 2*H*DK + H*DV
#define MTOK 4096          // B*T

// ---------------- scratch (device globals; no allocation allowed) ----------------
__device__ float g_mixed[(size_t)MTOK * CDIM];
__device__ float g_y[(size_t)MTOK * CDIM];
__device__ float g_qn[(size_t)MTOK * 2048];
__device__ float g_kn[(size_t)MTOK * 2048];
__device__ float g_beta[(size_t)MTOK * HH];
__device__ float g_decay[(size_t)MTOK * HH];
__device__ float g_o[(size_t)MTOK * 2048];
__device__ float g_z[(size_t)MTOK * 2048];

// bf16 hi/lo pre-split operands
__device__ __nv_bfloat16 g_xh[(size_t)MTOK * DM];
__device__ __nv_bfloat16 g_xl[(size_t)MTOK * DM];
__device__ __nv_bfloat16 g_wqh[(size_t)CDIM * DM];
__device__ __nv_bfloat16 g_wql[(size_t)CDIM * DM];
__device__ __nv_bfloat16 g_wzh[(size_t)2048 * DM];
__device__ __nv_bfloat16 g_wzl[(size_t)2048 * DM];
__device__ __nv_bfloat16 g_woh[(size_t)2048 * 2048];
__device__ __nv_bfloat16 g_wol[(size_t)2048 * 2048];
__device__ __nv_bfloat16 g_onh[(size_t)MTOK * 2048];
__device__ __nv_bfloat16 g_onl[(size_t)MTOK * 2048];

// ---------------- helpers ----------------
__device__ __forceinline__ void cp16(unsigned int dst, const void* src) {
    asm volatile("cp.async.cg.shared.global [%0], [%1], 16;" ::"r"(dst), "l"(src));
}

__device__ __forceinline__ unsigned short bfbits(__nv_bfloat16 v) {
    return *reinterpret_cast<unsigned short*>(&v);
}

__device__ __forceinline__ void ldsm4(unsigned int* r, unsigned int addr) {
    asm volatile("ldmatrix.sync.aligned.m8n8.x4.shared.b16 {%0,%1,%2,%3}, [%4];"
                 : "=r"(r[0]), "=r"(r[1]), "=r"(r[2]), "=r"(r[3])
                 : "r"(addr));
}

// ---------------- bf16 hi/lo split ----------------
__global__ __launch_bounds__(256) void split_bf(const float* __restrict__ s,
                                                __nv_bfloat16* __restrict__ h,
                                                __nv_bfloat16* __restrict__ l, int n4) {
    int i = blockIdx.x * 256 + threadIdx.x;
    if (i >= n4) return;
    float4 v = ((const float4*)s)[i];
    __nv_bfloat16 h0 = __float2bfloat16(v.x);
    __nv_bfloat16 h1 = __float2bfloat16(v.y);
    __nv_bfloat16 h2 = __float2bfloat16(v.z);
    __nv_bfloat16 h3 = __float2bfloat16(v.w);
    __nv_bfloat16 l0 = __float2bfloat16(v.x - __bfloat162float(h0));
    __nv_bfloat16 l1 = __float2bfloat16(v.y - __bfloat162float(h1));
    __nv_bfloat16 l2 = __float2bfloat16(v.z - __bfloat162float(h2));
    __nv_bfloat16 l3 = __float2bfloat16(v.w - __bfloat162float(h3));
    uint2 ho, lo;
    ho.x = ((unsigned int)bfbits(h1) << 16) | bfbits(h0);
    ho.y = ((unsigned int)bfbits(h3) << 16) | bfbits(h2);
    lo.x = ((unsigned int)bfbits(l1) << 16) | bfbits(l0);
    lo.y = ((unsigned int)bfbits(l3) << 16) | bfbits(l2);
    ((uint2*)h)[i] = ho;
    ((uint2*)l)[i] = lo;
}

// ---------------- 3xBF16 split tensor-core GEMM (ldmatrix inner loop) ----------
#define BKPAD 40
#define ROWB 80
#define TILE_ELE (128 * BKPAD)
#define TILE_B (TILE_ELE * 2)
#define STAGE_ELE (4 * TILE_ELE)
#define STAGE_B (4 * TILE_B)
#define GEMM_SMEM_B (2 * STAGE_B)

__device__ __forceinline__ void mma16(float* c, const unsigned int* a,
                                      unsigned int b0, unsigned int b1) {
    asm volatile(
        "mma.sync.aligned.m16n8k16.row.col.f32.bf16.bf16.f32 "
        "{%0,%1,%2,%3}, {%4,%5,%6,%7}, {%8,%9}, {%0,%1,%2,%3};"
        : "+f"(c[0]), "+f"(c[1]), "+f"(c[2]), "+f"(c[3])
        : "r"(a[0]), "r"(a[1]), "r"(a[2]), "r"(a[3]), "r"(b0), "r"(b1));
}

__device__ __forceinline__ void stage_tile(unsigned int dst, const __nv_bfloat16* src,
                                           int K, int tid) {
    const int row = tid >> 1;
    const int c0 = (tid & 1) * 2;
    cp16(dst + (unsigned int)(row * ROWB + c0 * 16), src + (size_t)row * K + c0 * 8);
    cp16(dst + (unsigned int)(row * ROWB + (c0 + 1) * 16), src + (size_t)row * K + (c0 + 1) * 8);
}

__device__ __forceinline__ void gemm_body(const __nv_bfloat16* Abh,
                                          const __nv_bfloat16* Abl,
                                          const __nv_bfloat16* Bbh,
                                          const __nv_bfloat16* Bbl,
                                          float* __restrict__ Crow0,
                                          int N, int K) {
    extern __shared__ __align__(16) __nv_bfloat16 sm[];
    const int tid = threadIdx.x;
    const int warp = tid >> 5, lane = tid & 31;
    const int wm = (warp & 3) * 32;
    const int wn = (warp >> 2) * 64;
    const int g = lane >> 2, tg = lane & 3;

    const unsigned int smb = (unsigned int)__cvta_generic_to_shared(sm);

    const unsigned int aLane =
        (unsigned int)((wm + (lane & 7) + ((lane & 8) ? 8 : 0)) * ROWB +
                       ((lane & 16) ? 16 : 0));
    const unsigned int bLane =
        (unsigned int)((wn + (lane & 7) + ((lane & 16) ? 8 : 0)) * ROWB +
                       ((lane & 8) ? 16 : 0));

    float acc[2][8][4];
#pragma unroll
    for (int mi = 0; mi < 2; mi++)
#pragma unroll
        for (int ni = 0; ni < 8; ni++)
#pragma unroll
            for (int r = 0; r < 4; r++) acc[mi][ni][r] = 0.f;

    stage_tile(smb + 0 * TILE_B, Abh, K, tid);
    stage_tile(smb + 1 * TILE_B, Abl, K, tid);
    stage_tile(smb + 2 * TILE_B, Bbh, K, tid);
    stage_tile(smb + 3 * TILE_B, Bbl, K, tid);
    asm volatile("cp.async.commit_group;");

    const int nk = K >> 5;
    for (int j = 0; j < nk; j++) {
        const int buf = j & 1;
        if (j + 1 < nk) {
            const unsigned int db = smb + (buf ^ 1) * STAGE_B;
            const int ko = (j + 1) * 32;
            stage_tile(db + 0 * TILE_B, Abh + ko, K, tid);
            stage_tile(db + 1 * TILE_B, Abl + ko, K, tid);
            stage_tile(db + 2 * TILE_B, Bbh + ko, K, tid);
            stage_tile(db + 3 * TILE_B, Bbl + ko, K, tid);
            asm volatile("cp.async.commit_group;");
            asm volatile("cp.async.wait_group 1;");
        } else {
            asm volatile("cp.async.wait_group 0;");
        }
        __syncthreads();

        const unsigned int tAh = smb + buf * STAGE_B;
        const unsigned int tAl = tAh + TILE_B;
        const unsigned int tBh = tAh + 2 * TILE_B;
        const unsigned int tBl = tAh + 3 * TILE_B;

#pragma unroll
        for (int kk = 0; kk < 32; kk += 16) {
            const unsigned int kb = (unsigned int)(kk * 2);
            unsigned int ah[2][4], al[2][4];
            ldsm4(ah[0], tAh + kb + aLane);
            ldsm4(ah[1], tAh + kb + aLane + 16 * ROWB);
            ldsm4(al[0], tAl + kb + aLane);
            ldsm4(al[1], tAl + kb + aLane + 16 * ROWB);
#pragma unroll
            for (int p = 0; p < 4; p++) {
                const unsigned int po = kb + (unsigned int)(p * 16 * ROWB) + bLane;
                unsigned int bh[4], bl[4];
                ldsm4(bh, tBh + po);
                ldsm4(bl, tBl + po);
#pragma unroll
                for (int mi = 0; mi < 2; mi++) {
                    mma16(acc[mi][2 * p], al[mi], bh[0], bh[1]);
                    mma16(acc[mi][2 * p], ah[mi], bl[0], bl[1]);
                    mma16(acc[mi][2 * p], ah[mi], bh[0], bh[1]);
                    mma16(acc[mi][2 * p + 1], al[mi], bh[2], bh[3]);
                    mma16(acc[mi][2 * p + 1], ah[mi], bl[2], bl[3]);
                    mma16(acc[mi][2 * p + 1], ah[mi], bh[2], bh[3]);
                }
            }
        }
        __syncthreads();
    }

#pragma unroll
    for (int mi = 0; mi < 2; mi++) {
#pragma unroll
        for (int ni = 0; ni < 8; ni++) {
            const int r0 = wm + mi * 16 + g;
            const int cc = wn + ni * 8 + tg * 2;
            *(float2*)(Crow0 + (size_t)r0 * N + cc) =
                make_float2(acc[mi][ni][0], acc[mi][ni][1]);
            *(float2*)(Crow0 + (size_t)(r0 + 8) * N + cc) =
                make_float2(acc[mi][ni][2], acc[mi][ni][3]);
        }
    }
}

__global__ __launch_bounds__(256, 2) void gemm_bf16(const __nv_bfloat16* __restrict__ Ah,
                                                    const __nv_bfloat16* __restrict__ Al,
                                                    const __nv_bfloat16* __restrict__ Bh,
                                                    const __nv_bfloat16* __restrict__ Bl,
                                                    float* __restrict__ C,
                                                    int M, int N, int K) {
    const int bm = blockIdx.y * 128, bn = blockIdx.x * 128;
    gemm_body(Ah + (size_t)bm * K, Al + (size_t)bm * K,
              Bh + (size_t)bn * K, Bl + (size_t)bn * K,
              C + (size_t)bm * N + bn, N, K);
}

__global__ __launch_bounds__(256, 2) void gemm_bf16_dual(
    const __nv_bfloat16* __restrict__ Ah, const __nv_bfloat16* __restrict__ Al,
    const __nv_bfloat16* __restrict__ B1h, const __nv_bfloat16* __restrict__ B1l,
    float* __restrict__ C1, int N1,
    const __nv_bfloat16* __restrict__ B2h, const __nv_bfloat16* __restrict__ B2l,
    float* __restrict__ C2, int N2, int K) {
    const int bm = blockIdx.y * 128;
    int bn = blockIdx.x * 128;
    const __nv_bfloat16 *Bh, *Bl;
    float* C;
    int N;
    if (bn < N1) {
        Bh = B1h; Bl = B1l; C = C1; N = N1;
    } else {
        bn -= N1;
        Bh = B2h; Bl = B2l; C = C2; N = N2;
    }
    gemm_body(Ah + (size_t)bm * K, Al + (size_t)bm * K,
              Bh + (size_t)bn * K, Bl + (size_t)bn * K,
              C + (size_t)bm * N + bn, N, K);
}

// ---------------- gates (tiled): 8 tokens per block, weights staged in smem ----
__global__ __launch_bounds__(256) void proj_gates(const float* __restrict__ x,
                                                  const float* __restrict__ w_b,
                                                  const float* __restrict__ w_a,
                                                  const float* __restrict__ dt_bias,
                                                  const float* __restrict__ A_log) {
    __shared__ float xs[8][260];
    __shared__ float ws[256][33];
    const int tid = threadIdx.x;
    const int d = tid & 31, tg = tid >> 5;
    const int m0 = blockIdx.x * 8;

    float acc = 0.f;
    for (int kc = 0; kc < DM; kc += 256) {
        __syncthreads();
        for (int idx = tid; idx < 8 * 256; idx += 256) {
            const int tok = idx >> 8, k = idx & 255;
            xs[tok][k] = x[(size_t)(m0 + tok) * DM + kc + k];
        }
        for (int idx = tid; idx < 32 * 256; idx += 256) {
            const int dd = idx >> 8, k = idx & 255;
            const float v = (dd < HH) ? w_b[(size_t)dd * DM + kc + k]
                                      : w_a[(size_t)(dd - HH) * DM + kc + k];
            ws[k][dd] = v;
        }
        __syncthreads();
#pragma unroll 8
        for (int k = 0; k < 256; k++) acc += xs[tg][k] * ws[k][d];
    }

    const int m = m0 + tg;
    if (d < HH) {
        g_beta[(size_t)m * HH + d] = 1.f / (1.f + expf(-acc));
    } else {
        const int h = d - HH;
        float sp = acc + dt_bias[h];
        sp = (sp > 20.f) ? sp : log1pf(expf(sp));
        g_decay[(size_t)m * HH + h] = expf(-expf(A_log[h]) * sp);
    }
}

// ---------------- causal depthwise conv + SiLU, fused q/k l2norm ----------------
__global__ __launch_bounds__(256) void conv_qk(const float* __restrict__ conv_w) {
    const int c = blockIdx.x * 256 + threadIdx.x;
    const int bt = blockIdx.y;
    const int t = bt & (TT - 1);
    const float* base = g_mixed + (size_t)bt * CDIM + c;
    float4 w = *(const float4*)(conv_w + (size_t)c * KW);
    float acc = w.w * base[0];
    if (t >= 1) acc += w.z * base[-(ptrdiff_t)CDIM];
    if (t >= 2) acc += w.y * base[-(ptrdiff_t)(2 * CDIM)];
    if (t >= 3) acc += w.x * base[-(ptrdiff_t)(3 * CDIM)];
    const float s = acc / (1.f + expf(-acc));

    if (blockIdx.x < 16) {
        __shared__ float red[8];
        float ss = s * s;
#pragma unroll
        for (int o = 16; o; o >>= 1) ss += __shfl_xor_sync(0xffffffffu, ss, o);
        const int warp = threadIdx.x >> 5;
        if ((threadIdx.x & 31) == 0) red[warp] = ss;
        __syncthreads();
        const int grp = threadIdx.x >> 7;
        const float tot = red[grp * 4] + red[grp * 4 + 1] + red[grp * 4 + 2] + red[grp * 4 + 3];
        const float r = rsqrtf(tot + 1e-6f);
        const int hh = c >> 7;
        float* dst = (hh < HH) ? g_qn : g_kn;
        dst[(size_t)bt * 2048 + (hh & 15) * DK + (c & 127)] = s * r;
    } else {
        g_y[(size_t)bt * CDIM + c] = s;
    }
}

// ---------------- sequential delta-rule scan (fp32, 8 kg x 32 j, 256 thr) ------
// smem k/q layout: 8 groups of 16 floats with stride 20 (chunk = 5*kg mod 8, all
// distinct -> conflict-free LDS.128 across the 8 kg phases).
__global__ __launch_bounds__(256) void scan_kernel(float* __restrict__ o) {
    const int bh = blockIdx.x;
    const int b = bh >> 4, h = bh & 15;
    const int jc = blockIdx.y;             // 0..3
    const int tid = threadIdx.x;
    const int jloc = tid >> 3;             // 0..31
    const int kg = tid & 7;                // 0..7

    __shared__ __align__(16) float ks[2][160], qs[2][160];
    __shared__ float vs[2][32], sc[2][2];
    float S[16];
#pragma unroll
    for (int i = 0; i < 16; i++) S[i] = 0.f;

    const size_t qkbase = ((size_t)b * TT) * 2048 + h * DK;
    const size_t vbase = ((size_t)b * TT) * CDIM + 2 * HH * DK + h * DV + jc * 32;
    const size_t gbase = ((size_t)b * TT) * HH + h;
    const size_t obase = ((size_t)b * TT) * 2048 + h * DV + jc * 32 + jloc;

    const int stslot = (tid >> 4) * 20 + (tid & 15);  // for tid < 128 staging

    float rk = 0.f, rq = 0.f, rv = 0.f;
    if (tid < 128) {
        rk = g_kn[qkbase + tid];
        rq = g_qn[qkbase + tid];
    }
    if (tid < 32) rv = g_y[vbase + tid];
    float rb = g_beta[gbase], rd = g_decay[gbase];
    if (tid < 128) {
        ks[0][stslot] = rk;
        qs[0][stslot] = rq;
    }
    if (tid < 32) vs[0][tid] = rv;
    if (tid == 0) { sc[0][0] = rb; sc[0][1] = rd; }
    __syncthreads();

    const int kbase = kg * 20;

    for (int t = 0; t < TT; t++) {
        const int cur = t & 1;
        if (t + 1 < TT) {
            const size_t to = (size_t)(t + 1);
            if (tid < 128) {
                rk = g_kn[qkbase + to * 2048 + tid];
                rq = g_qn[qkbase + to * 2048 + tid];
            }
            if (tid < 32) rv = g_y[vbase + to * CDIM + tid];
            rb = g_beta[gbase + to * HH];
            rd = g_decay[gbase + to * HH];
        }
        const float bet = sc[cur][0];
        const float dec = sc[cur][1];
        const float vv = vs[cur][jloc];

        float4 kf[4], qf[4];
#pragma unroll
        for (int i = 0; i < 4; i++) {
            kf[i] = *(const float4*)&ks[cur][kbase + 4 * i];
            qf[i] = *(const float4*)&qs[cur][kbase + 4 * i];
        }

        // kv = sum k*S  (4 chains of depth 4, tree combine)
        float p0, p1, p2, p3;
        p0 = kf[0].x * S[0];  p0 = fmaf(kf[0].y, S[1], p0);
        p0 = fmaf(kf[0].z, S[2], p0);  p0 = fmaf(kf[0].w, S[3], p0);
        p1 = kf[1].x * S[4];  p1 = fmaf(kf[1].y, S[5], p1);
        p1 = fmaf(kf[1].z, S[6], p1);  p1 = fmaf(kf[1].w, S[7], p1);
        p2 = kf[2].x * S[8];  p2 = fmaf(kf[2].y, S[9], p2);
        p2 = fmaf(kf[2].z, S[10], p2); p2 = fmaf(kf[2].w, S[11], p2);
        p3 = kf[3].x * S[12]; p3 = fmaf(kf[3].y, S[13], p3);
        p3 = fmaf(kf[3].z, S[14], p3); p3 = fmaf(kf[3].w, S[15], p3);
        float kv = (p0 + p1) + (p2 + p3);
        kv += __shfl_xor_sync(0xffffffffu, kv, 1);
        kv += __shfl_xor_sync(0xffffffffu, kv, 2);
        kv += __shfl_xor_sync(0xffffffffu, kv, 4);
        kv *= dec;

        const float delta = (vv - kv) * bet;

        // S = dec*S + k*delta; o = sum q*S  (4 chains + tree)
        float o0, o1, o2, o3;
#pragma unroll
        for (int i = 0; i < 4; i++) {
            const float4 kk = kf[i];
            S[4 * i + 0] = fmaf(dec, S[4 * i + 0], kk.x * delta);
            S[4 * i + 1] = fmaf(dec, S[4 * i + 1], kk.y * delta);
            S[4 * i + 2] = fmaf(dec, S[4 * i + 2], kk.z * delta);
            S[4 * i + 3] = fmaf(dec, S[4 * i + 3], kk.w * delta);
        }
        o0 = qf[0].x * S[0];  o0 = fmaf(qf[0].y, S[1], o0);
        o0 = fmaf(qf[0].z, S[2], o0);  o0 = fmaf(qf[0].w, S[3], o0);
        o1 = qf[1].x * S[4];  o1 = fmaf(qf[1].y, S[5], o1);
        o1 = fmaf(qf[1].z, S[6], o1);  o1 = fmaf(qf[1].w, S[7], o1);
        o2 = qf[2].x * S[8];  o2 = fmaf(qf[2].y, S[9], o2);
        o2 = fmaf(qf[2].z, S[10], o2); o2 = fmaf(qf[2].w, S[11], o2);
        o3 = qf[3].x * S[12]; o3 = fmaf(qf[3].y, S[13], o3);
        o3 = fmaf(qf[3].z, S[14], o3); o3 = fmaf(qf[3].w, S[15], o3);
        float oacc = (o0 + o1) + (o2 + o3);
        oacc += __shfl_xor_sync(0xffffffffu, oacc, 1);
        oacc += __shfl_xor_sync(0xffffffffu, oacc, 2);
        oacc += __shfl_xor_sync(0xffffffffu, oacc, 4);
        if (kg == 0) o[obase + (size_t)t * 2048] = oacc;

        if (t + 1 < TT) {
            const int nxt = cur ^ 1;
            if (tid < 128) {
                ks[nxt][stslot] = rk;
                qs[nxt][stslot] = rq;
            }
            if (tid < 32) vs[nxt][tid] = rv;
            if (tid == 0) { sc[nxt][0] = rb; sc[nxt][1] = rd; }
        }
        __syncthreads();
    }
}

// ---------------- gated RMSNorm per head + fused bf16 split ----------------
__global__ __launch_bounds__(128) void gated_norm(const float* __restrict__ norm_w) {
    const int g = blockIdx.x;  // bt*16 + h
    float u = g_o[(size_t)g * DV + threadIdx.x];
    float s = u * u;
#pragma unroll
    for (int o = 16; o; o >>= 1) s += __shfl_xor_sync(0xffffffffu, s, o);
    __shared__ float red[4];
    if ((threadIdx.x & 31) == 0) red[threadIdx.x >> 5] = s;
    __syncthreads();
    float tot = red[0] + red[1] + red[2] + red[3];
    float r = rsqrtf(tot * (1.f / DV) + 1e-6f);
    float zz = g_z[(size_t)g * DV + threadIdx.x];
    float sil = zz / (1.f + expf(-zz));
    const float val = u * r * norm_w[threadIdx.x] * sil;
    __nv_bfloat16 hv = __float2bfloat16(val);
    __nv_bfloat16 lv = __float2bfloat16(val - __bfloat162float(hv));
    g_onh[(size_t)g * DV + threadIdx.x] = hv;
    g_onl[(size_t)g * DV + threadIdx.x] = lv;
}

// ---------------- launch ----------------
extern "C" void kernel_launch(void* const* d_in, const int* in_sizes, int n_in,
                              void* d_out, int out_size) {
    const float* x = (const float*)d_in[0];
    const float* w_qkv = (const float*)d_in[1];
    const float* conv_w = (const float*)d_in[2];
    const float* w_z = (const float*)d_in[3];
    const float* w_b = (const float*)d_in[4];
    const float* w_a = (const float*)d_in[5];
    const float* dt_bias = (const float*)d_in[6];
    const float* A_log = (const float*)d_in[7];
    const float* norm_w = (const float*)d_in[8];
    const float* w_out = (const float*)d_in[9];
    float* out = (float*)d_out;

    float *mixed, *z, *o;
    __nv_bfloat16 *xh, *xl, *wqh, *wql, *wzh, *wzl, *woh, *wol, *onh, *onl;
    cudaGetSymbolAddress((void**)&mixed, g_mixed);
    cudaGetSymbolAddress((void**)&z, g_z);
    cudaGetSymbolAddress((void**)&o, g_o);
    cudaGetSymbolAddress((void**)&xh, g_xh);
    cudaGetSymbolAddress((void**)&xl, g_xl);
    cudaGetSymbolAddress((void**)&wqh, g_wqh);
    cudaGetSymbolAddress((void**)&wql, g_wql);
    cudaGetSymbolAddress((void**)&wzh, g_wzh);
    cudaGetSymbolAddress((void**)&wzl, g_wzl);
    cudaGetSymbolAddress((void**)&woh, g_woh);
    cudaGetSymbolAddress((void**)&wol, g_wol);
    cudaGetSymbolAddress((void**)&onh, g_onh);
    cudaGetSymbolAddress((void**)&onl, g_onl);

    cudaFuncSetAttribute(gemm_bf16, cudaFuncAttributeMaxDynamicSharedMemorySize, GEMM_SMEM_B);
    cudaFuncSetAttribute(gemm_bf16_dual, cudaFuncAttributeMaxDynamicSharedMemorySize,
                         GEMM_SMEM_B);

    // bf16 hi/lo pre-splits
    split_bf<<<(MTOK * DM / 4 + 255) / 256, 256>>>(x, xh, xl, MTOK * DM / 4);
    split_bf<<<(CDIM * DM / 4 + 255) / 256, 256>>>(w_qkv, wqh, wql, CDIM * DM / 4);
    split_bf<<<(2048 * DM / 4 + 255) / 256, 256>>>(w_z, wzh, wzl, 2048 * DM / 4);
    split_bf<<<(2048 * 2048 / 4 + 255) / 256, 256>>>(w_out, woh, wol, 2048 * 2048 / 4);

    // fused qkv + z projection
    gemm_bf16_dual<<<dim3((CDIM + 2048) / 128, MTOK / 128), 256, GEMM_SMEM_B>>>(
        xh, xl, wqh, wql, mixed, CDIM, wzh, wzl, z, 2048, DM);
    // gates (tiled)
    proj_gates<<<MTOK / 8, 256>>>(x, w_b, w_a, dt_bias, A_log);
    // conv + silu + fused q/k l2norm
    conv_qk<<<dim3(CDIM / 256, MTOK), 256>>>(conv_w);
    // scan
    scan_kernel<<<dim3(BB * HH, 4), 256>>>(o);
    // gated rmsnorm + fused on-split
    gated_norm<<<MTOK * HH, 128>>>(norm_w);
    // out = on @ w_out^T
    gemm_bf16<<<dim3(2048 / 128, MTOK / 128), 256, GEMM_SMEM_B>>>(onh, onl, woh, wol, out,
                                                                  MTOK, 2048, DM);
}